// round 4
// baseline (speedup 1.0000x reference)
#include <cuda_runtime.h>
#include <cstdint>
#include <math.h>

#define BB 4
#define SS 4096
#define DD 256
#define HH 400
#define BSROWS (BB*SS)

// ---- scratch ----
__device__ float g_Q[BSROWS*DD];
__device__ float g_K[BSROWS*DD];
__device__ float g_V[BSROWS*DD];
__device__ float g_T[BSROWS*DD];
__device__ float g_X[BSROWS*DD];
__device__ float g_Y[BSROWS*DD];
__device__ float g_H[BSROWS*HH];

// ============================================================
// helpers
// ============================================================
__device__ __forceinline__ float tf32r(float x) {
    float r; asm("cvt.rna.tf32.f32 %0, %1;" : "=f"(r) : "f"(x)); return r;
}
__device__ __forceinline__ uint32_t smem_u32(const void* p) {
    uint32_t a;
    asm("{ .reg .u64 t; cvta.to.shared.u64 t, %1; cvt.u32.u64 %0, t; }" : "=r"(a) : "l"(p));
    return a;
}
__device__ __forceinline__ void mma8(float c[4], const uint32_t a[4], const uint32_t b[2]) {
    asm volatile(
        "mma.sync.aligned.m16n8k8.row.col.f32.tf32.tf32.f32 "
        "{%0,%1,%2,%3}, {%4,%5,%6,%7}, {%8,%9}, {%0,%1,%2,%3};"
        : "+f"(c[0]), "+f"(c[1]), "+f"(c[2]), "+f"(c[3])
        : "r"(a[0]), "r"(a[1]), "r"(a[2]), "r"(a[3]), "r"(b[0]), "r"(b[1]));
}
__device__ __forceinline__ void ldm_x4(uint32_t r[4], uint32_t addr) {
    asm volatile("ldmatrix.sync.aligned.m8n8.x4.shared.b16 {%0,%1,%2,%3}, [%4];"
                 : "=r"(r[0]), "=r"(r[1]), "=r"(r[2]), "=r"(r[3]) : "r"(addr));
}
__device__ __forceinline__ void ldm_x2(uint32_t r[2], uint32_t addr) {
    asm volatile("ldmatrix.sync.aligned.m8n8.x2.shared.b16 {%0,%1}, [%2];"
                 : "=r"(r[0]), "=r"(r[1]) : "r"(addr));
}

// ============================================================
// Flash attention, tf32 HMMA + ldmatrix.
// CTA: 64 queries, 256 threads (8 warps = 4 row-groups x 2 halves).
// K/V chunks of 64 keys; V staged transposed Vt[d][k].
// ============================================================
#define FBQ 64
#define FBK 64
#define QSTR 260
#define KSTR 260
#define VSTR 68
#define SSTR 68
// f32 offsets in dynamic smem
#define OQ  0
#define OK  16640                 // 64*260
#define OVT 33280                 // + 64*260
#define OS  50688                 // + 256*68
#define OM  55040                 // + 64*68
#define OL  55104
#define OA  55168
#define FL_FLOATS 55232           // *4 = 220928 bytes

__global__ void __launch_bounds__(256, 1)
flash_mma(const float* __restrict__ Qg, const float* __restrict__ Kg,
          const float* __restrict__ Vg, float* __restrict__ Og, int causal) {
    extern __shared__ float fs[];
    uint32_t sb = smem_u32(fs);
    int tid = threadIdx.x;
    int wid = tid >> 5, lane = tid & 31;
    int rg = wid & 3;          // row-group: rows 16*rg .. +15
    int h  = wid >> 2;         // half: score cols 32h / O cols 128h
    int lrow = lane >> 2;
    int lcol = lane & 3;
    int b = blockIdx.y, q0 = blockIdx.x * FBQ;

    // ---- stage Q (prescaled by 1/64, rna-tf32) ----
    {
        const float4* Qr = (const float4*)(Qg + ((size_t)b * SS + q0) * DD);
        #pragma unroll
        for (int p = 0; p < 16; p++) {
            int idx = tid + p * 256;
            int r = idx >> 6, c4 = idx & 63;
            float4 v = Qr[r * 64 + c4];
            v.x = tf32r(v.x * 0.015625f); v.y = tf32r(v.y * 0.015625f);
            v.z = tf32r(v.z * 0.015625f); v.w = tf32r(v.w * 0.015625f);
            *(float4*)&fs[OQ + r * QSTR + c4 * 4] = v;
        }
    }
    if (tid < FBQ) { fs[OM + tid] = -INFINITY; fs[OL + tid] = 0.0f; }

    float ofrag[16][4];
    #pragma unroll
    for (int nb = 0; nb < 16; nb++)
        #pragma unroll
        for (int j = 0; j < 4; j++) ofrag[nb][j] = 0.0f;

    // ldmatrix byte-address bases (per lane)
    uint32_t qa = sb + (uint32_t)(OQ  + (16 * rg  + (lane & 15)) * QSTR + (lane >> 4) * 4) * 4;
    uint32_t ka = sb + (uint32_t)(OK  + (32 * h   + (lane & 7 )) * KSTR + ((lane >> 3) & 1) * 4) * 4;
    uint32_t pa = sb + (uint32_t)(OS  + (16 * rg  + (lane & 15)) * SSTR + (lane >> 4) * 4) * 4;
    uint32_t va = sb + (uint32_t)(OVT + (128 * h  + (lane & 7 )) * VSTR + ((lane >> 3) & 1) * 4) * 4;

    int nc = causal ? (q0 / FBK + 1) : (SS / FBK);
    int vkr = tid & 63, vdseg = (tid >> 6) * 64;

    for (int c = 0; c < nc; c++) {
        int k0 = c * FBK;
        bool maskc = causal && (k0 == q0);

        // ---- stage K ----
        {
            const float4* Kr = (const float4*)(Kg + ((size_t)b * SS + k0) * DD);
            #pragma unroll
            for (int p = 0; p < 16; p++) {
                int idx = tid + p * 256;
                int r = idx >> 6, c4 = idx & 63;
                float4 v = Kr[r * 64 + c4];
                v.x = tf32r(v.x); v.y = tf32r(v.y); v.z = tf32r(v.z); v.w = tf32r(v.w);
                *(float4*)&fs[OK + r * KSTR + c4 * 4] = v;
            }
        }
        // ---- stage V transposed: Vt[d][k] ----
        {
            const float* Vb = Vg + ((size_t)b * SS + k0) * DD;
            #pragma unroll
            for (int j = 0; j < 16; j++) {
                int d0 = vdseg + j * 4;
                float4 v = *(const float4*)(Vb + (size_t)vkr * DD + d0);
                fs[OVT + (d0 + 0) * VSTR + vkr] = tf32r(v.x);
                fs[OVT + (d0 + 1) * VSTR + vkr] = tf32r(v.y);
                fs[OVT + (d0 + 2) * VSTR + vkr] = tf32r(v.z);
                fs[OVT + (d0 + 3) * VSTR + vkr] = tf32r(v.w);
            }
        }
        __syncthreads();   // (A)

        // ---- scores: warp (rg,h): S[16rg..+15][32h..+31] ----
        {
            float sfr[4][4];
            #pragma unroll
            for (int nb = 0; nb < 4; nb++)
                #pragma unroll
                for (int j = 0; j < 4; j++) sfr[nb][j] = 0.0f;

            #pragma unroll
            for (int kb = 0; kb < 32; kb++) {
                uint32_t a4[4];
                ldm_x4(a4, qa + kb * 32);
                #pragma unroll
                for (int nb = 0; nb < 4; nb++) {
                    uint32_t b2[2];
                    ldm_x2(b2, ka + (uint32_t)nb * (8 * KSTR * 4) + kb * 32);
                    mma8(sfr[nb], a4, b2);
                }
            }
            // mask + store S
            int grow0 = q0 + 16 * rg + lrow;
            #pragma unroll
            for (int nb = 0; nb < 4; nb++) {
                int cb0 = 32 * h + nb * 8 + 2 * lcol;
                float2 v0 = make_float2(sfr[nb][0], sfr[nb][1]);
                float2 v1 = make_float2(sfr[nb][2], sfr[nb][3]);
                if (maskc) {
                    int g = k0 + cb0;
                    if (g > grow0)         v0.x = -1e30f;
                    if (g + 1 > grow0)     v0.y = -1e30f;
                    if (g > grow0 + 8)     v1.x = -1e30f;
                    if (g + 1 > grow0 + 8) v1.y = -1e30f;
                }
                *(float2*)&fs[OS + (16 * rg + lrow) * SSTR + cb0] = v0;
                *(float2*)&fs[OS + (16 * rg + lrow + 8) * SSTR + cb0] = v1;
            }
        }
        __syncthreads();   // (B)

        // ---- online softmax: 4 threads per row, 16 cols each ----
        {
            int row = tid >> 2, seg = tid & 3;
            float* Sr = &fs[OS + row * SSTR + seg * 16];
            float4 x0 = ((float4*)Sr)[0];
            float4 x1 = ((float4*)Sr)[1];
            float4 x2 = ((float4*)Sr)[2];
            float4 x3 = ((float4*)Sr)[3];
            float mx = fmaxf(fmaxf(fmaxf(x0.x, x0.y), fmaxf(x0.z, x0.w)),
                       fmaxf(fmaxf(fmaxf(x1.x, x1.y), fmaxf(x1.z, x1.w)),
                       fmaxf(fmaxf(fmaxf(x2.x, x2.y), fmaxf(x2.z, x2.w)),
                             fmaxf(fmaxf(x3.x, x3.y), fmaxf(x3.z, x3.w)))));
            mx = fmaxf(mx, __shfl_xor_sync(0xffffffff, mx, 1));
            mx = fmaxf(mx, __shfl_xor_sync(0xffffffff, mx, 2));
            float mold = fs[OM + row];
            float mnew = fmaxf(mold, mx);
            float alpha = __expf(mold - mnew);
            float sum = 0.0f;
            #pragma unroll
            for (int q = 0; q < 4; q++) {
                float4* xp = (q == 0) ? &x0 : (q == 1) ? &x1 : (q == 2) ? &x2 : &x3;
                xp->x = __expf(xp->x - mnew); sum += xp->x; xp->x = tf32r(xp->x);
                xp->y = __expf(xp->y - mnew); sum += xp->y; xp->y = tf32r(xp->y);
                xp->z = __expf(xp->z - mnew); sum += xp->z; xp->z = tf32r(xp->z);
                xp->w = __expf(xp->w - mnew); sum += xp->w; xp->w = tf32r(xp->w);
            }
            ((float4*)Sr)[0] = x0; ((float4*)Sr)[1] = x1;
            ((float4*)Sr)[2] = x2; ((float4*)Sr)[3] = x3;
            sum += __shfl_xor_sync(0xffffffff, sum, 1);
            sum += __shfl_xor_sync(0xffffffff, sum, 2);
            if (seg == 0) {
                fs[OL + row] = fs[OL + row] * alpha + sum;
                fs[OM + row] = mnew;
                fs[OA + row] = alpha;
            }
        }
        __syncthreads();   // (C)

        // ---- PV: warp (rg,h): O[16rg..+15][128h..+127] += P * V ----
        {
            float al0 = fs[OA + 16 * rg + lrow];
            float al8 = fs[OA + 16 * rg + lrow + 8];
            #pragma unroll
            for (int nb = 0; nb < 16; nb++) {
                ofrag[nb][0] *= al0; ofrag[nb][1] *= al0;
                ofrag[nb][2] *= al8; ofrag[nb][3] *= al8;
            }
            #pragma unroll
            for (int kb = 0; kb < 8; kb++) {
                uint32_t a4[4];
                ldm_x4(a4, pa + kb * 32);
                #pragma unroll
                for (int nb = 0; nb < 16; nb++) {
                    uint32_t b2[2];
                    ldm_x2(b2, va + (uint32_t)nb * (8 * VSTR * 4) + kb * 32);
                    mma8(ofrag[nb], a4, b2);
                }
            }
        }
        __syncthreads();   // (D)
    }

    // ---- epilogue ----
    {
        int row = 16 * rg + lrow;
        float inv0 = 1.0f / fs[OL + row];
        float inv8 = 1.0f / fs[OL + row + 8];
        float* Or0 = Og + ((size_t)b * SS + q0 + row) * DD;
        float* Or8 = Or0 + 8 * DD;
        #pragma unroll
        for (int nb = 0; nb < 16; nb++) {
            int col = 128 * h + nb * 8 + 2 * lcol;
            *(float2*)&Or0[col] = make_float2(ofrag[nb][0] * inv0, ofrag[nb][1] * inv0);
            *(float2*)&Or8[col] = make_float2(ofrag[nb][2] * inv8, ofrag[nb][3] * inv8);
        }
    }
}

// ============================================================
// tf32 HMMA GEMM with ldmatrix: C[M,N]=A[M,K]*W[K,N] (+bias,+leaky)
// BM=128, BN=64, BK=32, 256 threads (8 warps = 4m x 2n).
// M%128==0, K%16==0 required; N, K-tail guarded.
// ============================================================
#define GSTR 36    // 144B: ldmatrix-friendly (== 16 mod 128)

template<int BIAS, int LEAKY>
__global__ void __launch_bounds__(256)
gemm_tc(const float* __restrict__ A, const float* __restrict__ W,
        const float* __restrict__ bias, float* __restrict__ C,
        int M, int N, int K) {
    __shared__ float As[128 * GSTR];
    __shared__ float Wt[64 * GSTR];
    int tid = threadIdx.x;
    int wid = tid >> 5, lane = tid & 31;
    int wm = wid & 3, wn = wid >> 2;
    int lrow = lane >> 2, lcol = lane & 3;
    int rb = blockIdx.y * 128, cb = blockIdx.x * 64;

    float cfr[2][4][4];
    #pragma unroll
    for (int mt = 0; mt < 2; mt++)
        #pragma unroll
        for (int nb = 0; nb < 4; nb++)
            #pragma unroll
            for (int j = 0; j < 4; j++) cfr[mt][nb][j] = 0.0f;

    uint32_t sbA = smem_u32(As), sbW = smem_u32(Wt);
    uint32_t aa = sbA + (uint32_t)((32 * wm + (lane & 15)) * GSTR + (lane >> 4) * 4) * 4;
    uint32_t wa = sbW + (uint32_t)((32 * wn + (lane & 7)) * GSTR + ((lane >> 3) & 1) * 4) * 4;

    int arow = tid >> 1, akseg = (tid & 1) * 16;
    int wkk = tid & 31;           // == lane
    int wn4 = wid;                // 0..7

    for (int k0 = 0; k0 < K; k0 += 32) {
        // ---- stage A tile 128x32 ----
        #pragma unroll
        for (int q = 0; q < 4; q++) {
            int off = akseg + q * 4;
            float4 v;
            if (k0 + off < K) {
                v = *(const float4*)&A[(size_t)(rb + arow) * K + k0 + off];
                v.x = tf32r(v.x); v.y = tf32r(v.y); v.z = tf32r(v.z); v.w = tf32r(v.w);
            } else {
                v = make_float4(0.f, 0.f, 0.f, 0.f);
            }
            *(float4*)&As[arow * GSTR + off] = v;
        }
        // ---- stage W tile 32x64, transposed -> Wt[n][k] ----
        #pragma unroll
        for (int q = 0; q < 2; q++) {
            int ncol = wn4 * 8 + q * 4;
            int col = cb + ncol;
            float4 v;
            if (k0 + wkk < K && col < N) {
                v = *(const float4*)&W[(size_t)(k0 + wkk) * N + col];
                v.x = tf32r(v.x); v.y = tf32r(v.y); v.z = tf32r(v.z); v.w = tf32r(v.w);
            } else {
                v = make_float4(0.f, 0.f, 0.f, 0.f);
            }
            Wt[(ncol + 0) * GSTR + wkk] = v.x;
            Wt[(ncol + 1) * GSTR + wkk] = v.y;
            Wt[(ncol + 2) * GSTR + wkk] = v.z;
            Wt[(ncol + 3) * GSTR + wkk] = v.w;
        }
        __syncthreads();

        #pragma unroll
        for (int kb = 0; kb < 4; kb++) {
            uint32_t a0[4], a1[4];
            ldm_x4(a0, aa + kb * 32);
            ldm_x4(a1, aa + 16 * GSTR * 4 + kb * 32);
            #pragma unroll
            for (int nb = 0; nb < 4; nb++) {
                uint32_t b2[2];
                ldm_x2(b2, wa + (uint32_t)nb * (8 * GSTR * 4) + kb * 32);
                mma8(cfr[0][nb], a0, b2);
                mma8(cfr[1][nb], a1, b2);
            }
        }
        __syncthreads();
    }

    // ---- epilogue ----
    #pragma unroll
    for (int mt = 0; mt < 2; mt++) {
        int r0 = rb + 32 * wm + mt * 16 + lrow;
        #pragma unroll
        for (int nb = 0; nb < 4; nb++) {
            int col = cb + 32 * wn + nb * 8 + 2 * lcol;
            if (col < N) {
                float v00 = cfr[mt][nb][0], v01 = cfr[mt][nb][1];
                float v10 = cfr[mt][nb][2], v11 = cfr[mt][nb][3];
                if (BIAS) {
                    float b0 = bias[col], b1 = bias[col + 1];
                    v00 += b0; v01 += b1; v10 += b0; v11 += b1;
                }
                if (LEAKY) {
                    v00 = (v00 > 0.0f) ? v00 : 0.2f * v00;
                    v01 = (v01 > 0.0f) ? v01 : 0.2f * v01;
                    v10 = (v10 > 0.0f) ? v10 : 0.2f * v10;
                    v11 = (v11 > 0.0f) ? v11 : 0.2f * v11;
                }
                *(float2*)&C[(size_t)r0 * N + col] = make_float2(v00, v01);
                *(float2*)&C[(size_t)(r0 + 8) * N + col] = make_float2(v10, v11);
            }
        }
    }
}

// ============================================================
// out = LayerNorm(a + b), eps = 1e-3
// ============================================================
__global__ void add_ln_kernel(const float* __restrict__ a, const float* __restrict__ bvec,
                              const float* __restrict__ gamma, const float* __restrict__ beta,
                              float* __restrict__ out) {
    int row = blockIdx.x;
    int d = threadIdx.x;
    float v = a[row * DD + d] + bvec[row * DD + d];

    __shared__ float red[8];
    float sum = v;
    #pragma unroll
    for (int off = 16; off > 0; off >>= 1) sum += __shfl_xor_sync(0xffffffff, sum, off);
    if ((d & 31) == 0) red[d >> 5] = sum;
    __syncthreads();
    float tot = 0.0f;
    #pragma unroll
    for (int i = 0; i < 8; i++) tot += red[i];
    float mu = tot * (1.0f / DD);

    float dv = v - mu;
    float sq = dv * dv;
    #pragma unroll
    for (int off = 16; off > 0; off >>= 1) sq += __shfl_xor_sync(0xffffffff, sq, off);
    __syncthreads();
    if ((d & 31) == 0) red[d >> 5] = sq;
    __syncthreads();
    float var = 0.0f;
    #pragma unroll
    for (int i = 0; i < 8; i++) var += red[i];
    var *= (1.0f / DD);

    out[row * DD + d] = dv * rsqrtf(var + 1e-3f) * gamma[d] + beta[d];
}

// ============================================================
extern "C" void kernel_launch(void* const* d_in, const int* in_sizes, int n_in,
                              void* d_out, int out_size) {
    const float* inputs = (const float*)d_in[0];
    const float* ctx    = (const float*)d_in[1];
    const float* sa_Wk  = (const float*)d_in[2];
    const float* sa_Wv  = (const float*)d_in[3];
    const float* sa_Wq  = (const float*)d_in[4];
    const float* ca_Wk  = (const float*)d_in[5];
    const float* ca_Wv  = (const float*)d_in[6];
    const float* ca_Wq  = (const float*)d_in[7];
    const float* W1     = (const float*)d_in[8];
    const float* b1     = (const float*)d_in[9];
    const float* W2     = (const float*)d_in[10];
    const float* b2     = (const float*)d_in[11];
    const float* gamma  = (const float*)d_in[12];
    const float* beta   = (const float*)d_in[13];
    float* out = (float*)d_out;

    float *Qp, *Kp, *Vp, *Tp, *Xp, *Yp, *Hp;
    cudaGetSymbolAddress((void**)&Qp, g_Q);
    cudaGetSymbolAddress((void**)&Kp, g_K);
    cudaGetSymbolAddress((void**)&Vp, g_V);
    cudaGetSymbolAddress((void**)&Tp, g_T);
    cudaGetSymbolAddress((void**)&Xp, g_X);
    cudaGetSymbolAddress((void**)&Yp, g_Y);
    cudaGetSymbolAddress((void**)&Hp, g_H);

    const int flash_smem = FL_FLOATS * 4;
    cudaFuncSetAttribute(flash_mma, cudaFuncAttributeMaxDynamicSharedMemorySize, flash_smem);

    dim3 gD(DD / 64, BSROWS / 128);
    dim3 gH((HH + 63) / 64, BSROWS / 128);
    dim3 fg(SS / FBQ, BB);

    // 1) self-attention (causal)
    gemm_tc<0, 0><<<gD, 256>>>(inputs, sa_Wk, nullptr, Kp, BSROWS, DD, DD);
    gemm_tc<0, 0><<<gD, 256>>>(inputs, sa_Wv, nullptr, Vp, BSROWS, DD, DD);
    gemm_tc<0, 0><<<gD, 256>>>(inputs, sa_Wq, nullptr, Qp, BSROWS, DD, DD);
    flash_mma<<<fg, 256, flash_smem>>>(Qp, Kp, Vp, Tp, 1);
    add_ln_kernel<<<BSROWS, 256>>>(Tp, inputs, gamma, beta, Xp);

    // 2) cross-attention
    gemm_tc<0, 0><<<gD, 256>>>(ctx, ca_Wk, nullptr, Kp, BSROWS, DD, DD);
    gemm_tc<0, 0><<<gD, 256>>>(ctx, ca_Wv, nullptr, Vp, BSROWS, DD, DD);
    gemm_tc<0, 0><<<gD, 256>>>(Xp, ca_Wq, nullptr, Qp, BSROWS, DD, DD);
    flash_mma<<<fg, 256, flash_smem>>>(Qp, Kp, Vp, Tp, 0);
    add_ln_kernel<<<BSROWS, 256>>>(Tp, Xp, gamma, beta, Yp);

    // 3) FFN
    gemm_tc<1, 1><<<gH, 256>>>(Yp, W1, b1, Hp, BSROWS, HH, DD);
    gemm_tc<1, 0><<<gD, 256>>>(Hp, W2, b2, Tp, BSROWS, DD, HH);
    add_ln_kernel<<<BSROWS, 256>>>(Tp, Yp, gamma, beta, out);
}